// round 2
// baseline (speedup 1.0000x reference)
#include <cuda_runtime.h>

// out[e,b,o] = sum_n x[e,b,n] * W[e,o,n] + b[e,o]
// E=50000, B=512, N=2, O=2. Pure HBM-streaming: 410 MB compulsory traffic.
//
// Layout exploitation:
//   x   (E,B,2) fp32 -> float4 covers (e, 2 batch rows)   : x4[e*256 + t]
//   out (E,B,2) fp32 -> same shape                        : out4[e*256 + t]
//   W   (E,2,2) fp32 -> float4 per edge (w00,w01,w10,w11) : W4[e]
//   b   (E,2)   fp32 -> float2 per edge                   : b2[e]
//
// One block per edge, 256 threads, 2 batch rows per thread. W/b loads are
// uniform per block -> broadcast from L2; x/out are perfectly coalesced
// 128-bit streams.

static constexpr int B_HALF = 256;   // 512 batch / 2 rows-per-thread

__global__ __launch_bounds__(256) void per_edge_linear_kernel(
    const float4* __restrict__ x4,
    const float4* __restrict__ W4,
    const float2* __restrict__ b2,
    float4* __restrict__ out4)
{
    const int e = blockIdx.x;

    const float4 w  = __ldg(&W4[e]);   // w.x=W[e][0][0] w.y=W[e][0][1] w.z=W[e][1][0] w.w=W[e][1][1]
    const float2 bb = __ldg(&b2[e]);

    const int idx = e * B_HALF + threadIdx.x;
    const float4 xv = x4[idx];         // (x[b][0], x[b][1], x[b+1][0], x[b+1][1])

    float4 o;
    o.x = fmaf(xv.x, w.x, fmaf(xv.y, w.y, bb.x));  // out[b][0]
    o.y = fmaf(xv.x, w.z, fmaf(xv.y, w.w, bb.y));  // out[b][1]
    o.z = fmaf(xv.z, w.x, fmaf(xv.w, w.y, bb.x));  // out[b+1][0]
    o.w = fmaf(xv.z, w.z, fmaf(xv.w, w.w, bb.y));  // out[b+1][1]

    out4[idx] = o;
}

extern "C" void kernel_launch(void* const* d_in, const int* in_sizes, int n_in,
                              void* d_out, int out_size)
{
    const float4* x4 = (const float4*)d_in[0];   // x (E,B,N) fp32
    const float4* W4 = (const float4*)d_in[1];   // W (E,O,N) fp32
    const float2* b2 = (const float2*)d_in[2];   // b (E,O)   fp32
    float4* out4     = (float4*)d_out;           // out (E,B,O) fp32

    const int E = in_sizes[1] / 4;               // W has E*O*N = E*4 elements

    per_edge_linear_kernel<<<E, 256>>>(x4, W4, b2, out4);
}

// round 4
// speedup vs baseline: 1.0540x; 1.0540x over previous
#include <cuda_runtime.h>

// out[e,b,o] = sum_n x[e,b,n] * W[e,o,n] + b[e,o]
// E=50000, B=512, N=O=2. Pure HBM stream: 410 MB compulsory traffic.
//
// Design (R2 theory, hardened): 4 edges per block-iteration, each thread
// issues 4 independent front-batched float4 x-loads (MLP_p1=4) to hide
// ~577-cycle DRAM latency at full bandwidth. Grid-stride over edge groups
// so correctness holds for any E / any grid (no divisibility assumptions,
// explicit tail). W/b are per-block uniform loads, L2-resident (<1 MB).
//
//   x   (E,B,2) fp32 -> float4 = 2 batch rows : x4[e*256 + t]
//   out (E,B,2) fp32 -> same                  : out4[e*256 + t]
//   W   (E,2,2) fp32 -> float4 per edge       : W4[e]
//   b   (E,2)   fp32 -> float2 per edge       : b2[e]

static constexpr int B_HALF = 256;  // 512 batch rows / 2 per thread
static constexpr int EPB    = 4;    // edges per block-iteration

__global__ __launch_bounds__(256) void per_edge_linear_kernel(
    const float4* __restrict__ x4,
    const float4* __restrict__ W4,
    const float2* __restrict__ b2,
    float4* __restrict__ out4,
    int E)
{
    const int t = threadIdx.x;
    const int num_groups = (E + EPB - 1) / EPB;

    for (int grp = blockIdx.x; grp < num_groups; grp += gridDim.x) {
        const int e0 = grp * EPB;

        if (e0 + EPB <= E) {
            // Full group: 4 independent streaming loads batched up front.
            float4 w[EPB];
            float2 bb[EPB];
            #pragma unroll
            for (int g = 0; g < EPB; ++g) {
                w[g]  = __ldg(&W4[e0 + g]);
                bb[g] = __ldg(&b2[e0 + g]);
            }

            float4 xv[EPB];
            #pragma unroll
            for (int g = 0; g < EPB; ++g)
                xv[g] = x4[(e0 + g) * B_HALF + t];

            #pragma unroll
            for (int g = 0; g < EPB; ++g) {
                float4 o;
                o.x = fmaf(xv[g].x, w[g].x, fmaf(xv[g].y, w[g].y, bb[g].x));
                o.y = fmaf(xv[g].x, w[g].z, fmaf(xv[g].y, w[g].w, bb[g].y));
                o.z = fmaf(xv[g].z, w[g].x, fmaf(xv[g].w, w[g].y, bb[g].x));
                o.w = fmaf(xv[g].z, w[g].z, fmaf(xv[g].w, w[g].w, bb[g].y));
                out4[(e0 + g) * B_HALF + t] = o;
            }
        } else {
            // Tail group (only if E % EPB != 0).
            for (int e = e0; e < E; ++e) {
                const float4 w  = __ldg(&W4[e]);
                const float2 bb = __ldg(&b2[e]);
                const float4 xv = x4[e * B_HALF + t];
                float4 o;
                o.x = fmaf(xv.x, w.x, fmaf(xv.y, w.y, bb.x));
                o.y = fmaf(xv.x, w.z, fmaf(xv.y, w.w, bb.y));
                o.z = fmaf(xv.z, w.x, fmaf(xv.w, w.y, bb.x));
                o.w = fmaf(xv.z, w.z, fmaf(xv.w, w.w, bb.y));
                out4[e * B_HALF + t] = o;
            }
        }
    }
}

extern "C" void kernel_launch(void* const* d_in, const int* in_sizes, int n_in,
                              void* d_out, int out_size)
{
    const float4* x4 = (const float4*)d_in[0];   // x (E,B,N) fp32
    const float4* W4 = (const float4*)d_in[1];   // W (E,O,N) fp32
    const float2* b2 = (const float2*)d_in[2];   // b (E,O)   fp32
    float4* out4     = (float4*)d_out;           // out (E,B,O) fp32

    const int E = in_sizes[1] / 4;               // W has E*O*N = E*4 elements
    int grid = (E + EPB - 1) / EPB;              // one block per group, grid-stride safe

    per_edge_linear_kernel<<<grid, 256>>>(x4, W4, b2, out4, E);
}